// round 1
// baseline (speedup 1.0000x reference)
#include <cuda_runtime.h>
#include <cuda_bf16.h>
#include <math.h>

#define BQ 900
#define BT 128
#define NCLS 91
#define NB 64
#define QPB 8

#define POS_INF __int_as_float(0x7f800000)

// ---------------------------------------------------------------------------
// Kernel 1: cost matrix.  One block handles (batch b, 8 query rows).
// 128 threads: thread t computes the cost against target t for each row.
// ---------------------------------------------------------------------------
__global__ void __launch_bounds__(128) cost_kernel(
    const float* __restrict__ logits,   // [B,Q,91]
    const float* __restrict__ pboxes,   // [B,Q,4]
    const int*   __restrict__ labels,   // [B,T]
    const float* __restrict__ tboxes,   // [B,T,4]
    float* __restrict__ Cout)           // [B,Q,T]
{
    const int b  = blockIdx.y;
    const int q0 = blockIdx.x * QPB;
    const int tid = threadIdx.x;  // 0..127

    __shared__ float s_tcx[BT], s_tcy[BT], s_tw[BT], s_th[BT];
    __shared__ float s_tx0[BT], s_ty0[BT], s_tx1[BT], s_ty1[BT], s_ta[BT];
    __shared__ int   s_lab[BT];
    __shared__ float s_log[NCLS];
    __shared__ float s_red[128];

    // Load targets for this batch (one target per thread)
    {
        const float* tb = tboxes + ((long)b * BT + tid) * 4;
        float cx = tb[0], cy = tb[1], w = tb[2], h = tb[3];
        s_tcx[tid] = cx; s_tcy[tid] = cy; s_tw[tid] = w; s_th[tid] = h;
        float x0 = cx - 0.5f * w, y0 = cy - 0.5f * h;
        float x1 = cx + 0.5f * w, y1 = cy + 0.5f * h;
        s_tx0[tid] = x0; s_ty0[tid] = y0; s_tx1[tid] = x1; s_ty1[tid] = y1;
        s_ta[tid]  = (x1 - x0) * (y1 - y0);
        s_lab[tid] = labels[b * BT + tid];
    }
    __syncthreads();

    for (int qi = 0; qi < QPB; qi++) {
        int q = q0 + qi;
        if (q >= BQ) break;

        const float* lrow = logits + ((long)b * BQ + q) * NCLS;
        if (tid < NCLS) s_log[tid] = lrow[tid];
        __syncthreads();

        // block max over 91 logits
        float v = (tid < NCLS) ? s_log[tid] : -POS_INF;
        s_red[tid] = v;
        __syncthreads();
        #pragma unroll
        for (int s = 64; s > 0; s >>= 1) {
            if (tid < s) s_red[tid] = fmaxf(s_red[tid], s_red[tid + s]);
            __syncthreads();
        }
        float m = s_red[0];
        __syncthreads();

        // block sum of exp(l - m)
        float e = (tid < NCLS) ? expf(s_log[tid] - m) : 0.0f;
        s_red[tid] = e;
        __syncthreads();
        #pragma unroll
        for (int s = 64; s > 0; s >>= 1) {
            if (tid < s) s_red[tid] = s_red[tid] + s_red[tid + s];
            __syncthreads();
        }
        float ssum = s_red[0];
        __syncthreads();

        // prediction box for this row (broadcast read)
        const float* pb = pboxes + ((long)b * BQ + q) * 4;
        float pcx = pb[0], pcy = pb[1], pw = pb[2], ph = pb[3];
        float px0 = pcx - 0.5f * pw, py0 = pcy - 0.5f * ph;
        float px1 = pcx + 0.5f * pw, py1 = pcy + 0.5f * ph;
        float parea = (px1 - px0) * (py1 - py0);

        // per-target cost (thread tid = target tid)
        float pl = expf(s_log[s_lab[tid]] - m) / ssum;
        float l1 = fabsf(pcx - s_tcx[tid]) + fabsf(pcy - s_tcy[tid])
                 + fabsf(pw - s_tw[tid])   + fabsf(ph - s_th[tid]);

        float ix0 = fmaxf(px0, s_tx0[tid]);
        float iy0 = fmaxf(py0, s_ty0[tid]);
        float ix1 = fminf(px1, s_tx1[tid]);
        float iy1 = fminf(py1, s_ty1[tid]);
        float iw  = fmaxf(ix1 - ix0, 0.0f);
        float ih  = fmaxf(iy1 - iy0, 0.0f);
        float inter = iw * ih;
        float uni   = parea + s_ta[tid] - inter;
        float iou   = inter / uni;

        float cx0 = fminf(px0, s_tx0[tid]);
        float cy0 = fminf(py0, s_ty0[tid]);
        float cx1 = fmaxf(px1, s_tx1[tid]);
        float cy1 = fmaxf(py1, s_ty1[tid]);
        float cw  = fmaxf(cx1 - cx0, 0.0f);
        float ch  = fmaxf(cy1 - cy0, 0.0f);
        float ac  = cw * ch;
        float giou = iou - (ac - uni) / ac;

        float cost = -pl + 5.0f * l1 - 2.0f * giou;
        Cout[((long)b * BQ + q) * BT + tid] = cost;
        __syncthreads();  // before s_log / s_red reuse
    }
}

// ---------------------------------------------------------------------------
// Kernel 2: greedy matching.  One 256-thread block per batch.
// Maintains per-row (min, argmin); only rows whose argmin column was removed
// get rescanned (expected ~Q*H(T) rescans total per batch).
// ---------------------------------------------------------------------------
__global__ void __launch_bounds__(256) greedy_kernel(
    const float* __restrict__ Cmat,   // [B,Q,T]
    float* __restrict__ out)          // [B*T src | B*T tgt | ...]
{
    const int b   = blockIdx.x;
    const int tid = threadIdx.x;       // 0..255
    const int lane = tid & 31;
    const int wid  = tid >> 5;         // 0..7
    const float* Cb = Cmat + (long)b * BQ * BT;

    __shared__ float rowmin[BQ];
    __shared__ int   rowarg[BQ];
    __shared__ unsigned char colrem[BT];
    __shared__ int   list_[BQ];
    __shared__ int   cnt;
    __shared__ float rv[256];
    __shared__ int   ri[256];
    __shared__ int   s_src[BT], s_tgt[BT];
    __shared__ int   s_bj;

    if (tid < BT) colrem[tid] = 0;

    // init per-row minima: one warp per row, lanes stride columns ascending
    for (int q = wid; q < BQ; q += 8) {
        const float* row = Cb + q * BT;
        float bv = POS_INF; int ba = BT;
        #pragma unroll
        for (int c = lane; c < BT; c += 32) {
            float v = row[c];
            if (v < bv) { bv = v; ba = c; }     // strict < keeps first (smallest c)
        }
        #pragma unroll
        for (int off = 16; off > 0; off >>= 1) {
            float ov = __shfl_down_sync(0xffffffffu, bv, off);
            int   oa = __shfl_down_sync(0xffffffffu, ba, off);
            if (ov < bv || (ov == bv && oa < ba)) { bv = ov; ba = oa; }
        }
        if (lane == 0) { rowmin[q] = bv; rowarg[q] = ba; }
    }
    __syncthreads();

    for (int t = 0; t < BT; t++) {
        // block argmin over row minima (tie -> smallest row index)
        float bv = POS_INF; int bi = BQ;
        for (int q = tid; q < BQ; q += 256) {
            float v = rowmin[q];
            if (v < bv) { bv = v; bi = q; }     // ascending q, strict <
        }
        rv[tid] = bv; ri[tid] = bi;
        __syncthreads();
        #pragma unroll
        for (int s = 128; s > 0; s >>= 1) {
            if (tid < s) {
                float ov = rv[tid + s]; int oi = ri[tid + s];
                if (ov < rv[tid] || (ov == rv[tid] && oi < ri[tid])) {
                    rv[tid] = ov; ri[tid] = oi;
                }
            }
            __syncthreads();
        }
        if (tid == 0) {
            int i = ri[0];
            int j = rowarg[i];
            s_src[t] = i; s_tgt[t] = j;
            s_bj = j;
            rowmin[i] = POS_INF;
            colrem[j] = 1;
            cnt = 0;
        }
        __syncthreads();

        // collect rows whose cached argmin just got removed
        int bj = s_bj;
        for (int q = tid; q < BQ; q += 256) {
            if (rowmin[q] != POS_INF && rowarg[q] == bj) {
                int p = atomicAdd(&cnt, 1);
                list_[p] = q;
            }
        }
        __syncthreads();

        // rescan those rows (warp per row) over still-active columns
        int n = cnt;
        for (int idx = wid; idx < n; idx += 8) {
            int q = list_[idx];
            const float* row = Cb + q * BT;
            float v2 = POS_INF; int a2 = BT;
            #pragma unroll
            for (int c = lane; c < BT; c += 32) {
                if (!colrem[c]) {
                    float v = row[c];
                    if (v < v2) { v2 = v; a2 = c; }
                }
            }
            #pragma unroll
            for (int off = 16; off > 0; off >>= 1) {
                float ov = __shfl_down_sync(0xffffffffu, v2, off);
                int   oa = __shfl_down_sync(0xffffffffu, a2, off);
                if (ov < v2 || (ov == v2 && oa < a2)) { v2 = ov; a2 = oa; }
            }
            if (lane == 0) { rowmin[q] = v2; rowarg[q] = a2; }
        }
        __syncthreads();
    }

    // write indices as floats: [B*T src][B*T tgt]
    if (tid < BT) {
        out[b * BT + tid]            = (float)s_src[tid];
        out[NB * BT + b * BT + tid]  = (float)s_tgt[tid];
    }
}

// ---------------------------------------------------------------------------
extern "C" void kernel_launch(void* const* d_in, const int* in_sizes, int n_in,
                              void* d_out, int out_size) {
    const float* logits = (const float*)d_in[0];   // [64,900,91]
    const float* pboxes = (const float*)d_in[1];   // [64,900,4]
    const int*   labels = (const int*)d_in[2];     // [64,128]
    const float* tboxes = (const float*)d_in[3];   // [64,128,4]
    float* out = (float*)d_out;

    // C lives in d_out after the two index blocks
    float* Cout = out + 2 * NB * BT;

    dim3 grid1((BQ + QPB - 1) / QPB, NB);
    cost_kernel<<<grid1, 128>>>(logits, pboxes, labels, tboxes, Cout);

    greedy_kernel<<<NB, 256>>>(Cout, out);
}